// round 1
// baseline (speedup 1.0000x reference)
#include <cuda_runtime.h>
#include <cuda_bf16.h>
#include <math.h>

#define N_NODES 50000
#define N_EDGES 500000
#define D_MODEL 128
#define EDGE_DIM 16
#define LN_EPS 1e-5f

// ---------------- scratch (static device globals; no allocs) ----------------
__device__ float g_h[(size_t)N_NODES * D_MODEL];      // x_src @ W_src^T
__device__ float g_hdst[(size_t)N_NODES * D_MODEL];   // x_dst @ W_dst^T + b
__device__ float g_gate[N_EDGES];
__device__ float g_deg[N_NODES];

// ---------------- K0: zero agg (d_out) + deg ----------------
__global__ void zero_kernel(float* __restrict__ out) {
    int i = blockIdx.x * blockDim.x + threadIdx.x;
    int stride = gridDim.x * blockDim.x;
    const int n4 = (N_NODES * D_MODEL) / 4;
    float4 z = make_float4(0.f, 0.f, 0.f, 0.f);
    for (int idx = i; idx < n4; idx += stride) ((float4*)out)[idx] = z;
    for (int idx = i; idx < N_NODES; idx += stride) g_deg[idx] = 0.f;
}

// ---------------- K1: node-side transforms (two GEMMs) ----------------
// out[n,f] = sum_d X[n,d] * W[f,d]  (+ bias for dst path)
// block = 256 threads (8 warps), tile = 64 rows x 128 cols, full K=128 in one pass.
// Shared: W transposed Wsh[d][f] (padded row 132 floats -> conflict-free LDS.128),
//         xs[64][128] (reads are warp-uniform -> broadcast).
#define WPAD 132
#define TRANSFORM_SMEM ((D_MODEL * WPAD + 64 * D_MODEL) * (int)sizeof(float))

__global__ void __launch_bounds__(256, 2) transform_kernel(
    const float* __restrict__ x_src, const float* __restrict__ x_dst,
    const float* __restrict__ W_src, const float* __restrict__ W_dst,
    const float* __restrict__ b_dst)
{
    extern __shared__ float smem[];
    float* Wsh = smem;                    // [128][132]
    float* xs  = smem + D_MODEL * WPAD;   // [64][128]

    const int which = blockIdx.y;
    const float* X = which ? x_dst : x_src;
    const float* W = which ? W_dst : W_src;
    float* OUT = which ? g_hdst : g_h;

    const int row0 = blockIdx.x * 64;
    const int tid  = threadIdx.x;

    // stage W transposed: Wsh[d*WPAD + f] = W[f*128 + d]
    for (int idx = tid; idx < D_MODEL * D_MODEL; idx += 256) {
        int f = idx >> 7, d = idx & 127;
        Wsh[d * WPAD + f] = W[idx];
    }
    // stage x rows (float4 coalesced)
    const int rows = min(64, N_NODES - row0);
    for (int idx = tid; idx < rows * 32; idx += 256) {
        int r = idx >> 5, c = idx & 31;
        ((float4*)xs)[r * 32 + c] = ((const float4*)(X + (size_t)(row0 + r) * D_MODEL))[c];
    }
    __syncthreads();

    const int lane = tid & 31;
    const int warp = tid >> 5;
    const int rbase = warp * 8;           // 8 rows per warp
    const float* xbase = xs + rbase * D_MODEL;

    float4 acc[8];
#pragma unroll
    for (int r = 0; r < 8; r++) acc[r] = make_float4(0.f, 0.f, 0.f, 0.f);

    const float4* Wv = (const float4*)Wsh;  // row stride = WPAD/4 = 33 float4

#pragma unroll 4
    for (int d = 0; d < D_MODEL; d++) {
        float4 w = Wv[d * 33 + lane];       // lane -> cols lane*4..lane*4+3
#pragma unroll
        for (int r = 0; r < 8; r++) {
            float xv = xbase[r * D_MODEL + d];   // warp-uniform -> broadcast
            acc[r].x += w.x * xv;
            acc[r].y += w.y * xv;
            acc[r].z += w.z * xv;
            acc[r].w += w.w * xv;
        }
    }

    float4 bias = make_float4(0.f, 0.f, 0.f, 0.f);
    if (which) bias = ((const float4*)b_dst)[lane];

#pragma unroll
    for (int r = 0; r < 8; r++) {
        int row = row0 + rbase + r;
        if (row < N_NODES) {
            float4 v;
            v.x = acc[r].x + bias.x;
            v.y = acc[r].y + bias.y;
            v.z = acc[r].z + bias.z;
            v.w = acc[r].w + bias.w;
            ((float4*)(OUT + (size_t)row * D_MODEL))[lane] = v;
        }
    }
}

// ---------------- K2: edge-gate MLP ----------------
// gate[e] = sigmoid( w2 . gelu(W1 @ ea + b1) + b2 )
// warp-per-edge; each lane owns 4 hidden rows of W1 in REGISTERS (f = lane + 32j),
// so the inner 64 FMA/lane run register-only (no LDS bandwidth bound).
__global__ void __launch_bounds__(256) gate_kernel(
    const float* __restrict__ edge_attr,
    const float* __restrict__ gate_w1, const float* __restrict__ gate_b1,
    const float* __restrict__ gate_w2, const float* __restrict__ gate_b2)
{
    const int lane = threadIdx.x & 31;

    float w1r[4][16], b1r[4], w2r[4];
#pragma unroll
    for (int j = 0; j < 4; j++) {
        int f = lane + 32 * j;
#pragma unroll
        for (int k = 0; k < 16; k++) w1r[j][k] = gate_w1[f * 16 + k];
        b1r[j] = gate_b1[f];
        w2r[j] = gate_w2[f];
    }
    const float b2 = gate_b2[0];

    int wid    = (blockIdx.x * blockDim.x + threadIdx.x) >> 5;
    int nwarps = (gridDim.x * blockDim.x) >> 5;

    for (int e = wid; e < N_EDGES; e += nwarps) {
        const float4* ea = (const float4*)(edge_attr + (size_t)e * EDGE_DIM);
        float4 e0 = ea[0], e1 = ea[1], e2 = ea[2], e3 = ea[3];
        float ev[16] = { e0.x, e0.y, e0.z, e0.w,
                         e1.x, e1.y, e1.z, e1.w,
                         e2.x, e2.y, e2.z, e2.w,
                         e3.x, e3.y, e3.z, e3.w };
        float acc = 0.f;
#pragma unroll
        for (int j = 0; j < 4; j++) {
            float h = b1r[j];
#pragma unroll
            for (int k = 0; k < 16; k++) h = fmaf(w1r[j][k], ev[k], h);
            float g = 0.5f * h * (1.f + erff(h * 0.70710678118654752f));  // exact gelu
            acc = fmaf(g, w2r[j], acc);
        }
#pragma unroll
        for (int off = 16; off; off >>= 1)
            acc += __shfl_xor_sync(0xffffffffu, acc, off);
        if (lane == 0)
            g_gate[e] = 1.f / (1.f + __expf(-(acc + b2)));
    }
}

// ---------------- K3: gather h[src] * gate -> red-add into out[dst] ----------------
__global__ void __launch_bounds__(256) scatter_kernel(
    const int* __restrict__ edge_src, const int* __restrict__ edge_dst,
    float* __restrict__ out)
{
    const int lane = threadIdx.x & 31;
    int wid    = (blockIdx.x * blockDim.x + threadIdx.x) >> 5;
    int nwarps = (gridDim.x * blockDim.x) >> 5;

    for (int e = wid; e < N_EDGES; e += nwarps) {
        int s = edge_src[e];
        int d = edge_dst[e];
        float g = g_gate[e];
        float4 h = ((const float4*)(g_h + (size_t)s * D_MODEL))[lane];
        float* dst = out + (size_t)d * D_MODEL + lane * 4;
        asm volatile("red.global.add.v4.f32 [%0], {%1, %2, %3, %4};"
                     :: "l"(dst), "f"(h.x * g), "f"(h.y * g),
                        "f"(h.z * g), "f"(h.w * g)
                     : "memory");
        if (lane == 0) atomicAdd(&g_deg[d], 1.f);
    }
}

// ---------------- K4: deg-norm + residual + LayerNorm + gelu ----------------
__global__ void __launch_bounds__(256) finalize_kernel(
    float* __restrict__ out,
    const float* __restrict__ ln_gamma, const float* __restrict__ ln_beta)
{
    const int lane = threadIdx.x & 31;
    int node = (blockIdx.x * blockDim.x + threadIdx.x) >> 5;
    if (node >= N_NODES) return;

    float invdeg = 1.f / fmaxf(g_deg[node], 1.f);
    float4 a  = ((const float4*)(out    + (size_t)node * D_MODEL))[lane];
    float4 hd = ((const float4*)(g_hdst + (size_t)node * D_MODEL))[lane];
    float4 v;
    v.x = a.x * invdeg + hd.x;
    v.y = a.y * invdeg + hd.y;
    v.z = a.z * invdeg + hd.z;
    v.w = a.w * invdeg + hd.w;

    float s  = v.x + v.y + v.z + v.w;
    float s2 = v.x * v.x + v.y * v.y + v.z * v.z + v.w * v.w;
#pragma unroll
    for (int off = 16; off; off >>= 1) {
        s  += __shfl_xor_sync(0xffffffffu, s,  off);
        s2 += __shfl_xor_sync(0xffffffffu, s2, off);
    }
    const float inv_d = 1.f / (float)D_MODEL;
    float mu   = s * inv_d;
    float var  = fmaxf(s2 * inv_d - mu * mu, 0.f);
    float rstd = rsqrtf(var + LN_EPS);

    float4 gm = ((const float4*)ln_gamma)[lane];
    float4 bt = ((const float4*)ln_beta)[lane];

    float y0 = (v.x - mu) * rstd * gm.x + bt.x;
    float y1 = (v.y - mu) * rstd * gm.y + bt.y;
    float y2 = (v.z - mu) * rstd * gm.z + bt.z;
    float y3 = (v.w - mu) * rstd * gm.w + bt.w;

    const float c = 0.70710678118654752f;
    float4 o;
    o.x = 0.5f * y0 * (1.f + erff(y0 * c));
    o.y = 0.5f * y1 * (1.f + erff(y1 * c));
    o.z = 0.5f * y2 * (1.f + erff(y2 * c));
    o.w = 0.5f * y3 * (1.f + erff(y3 * c));

    ((float4*)(out + (size_t)node * D_MODEL))[lane] = o;
}

// ---------------- launch ----------------
extern "C" void kernel_launch(void* const* d_in, const int* in_sizes, int n_in,
                              void* d_out, int out_size)
{
    const float* x_src     = (const float*)d_in[0];
    const float* x_dst     = (const float*)d_in[1];
    const int*   edge_src  = (const int*)  d_in[2];
    const int*   edge_dst  = (const int*)  d_in[3];
    const float* edge_attr = (const float*)d_in[4];
    const float* W_src     = (const float*)d_in[5];
    const float* W_dst     = (const float*)d_in[6];
    const float* b_dst     = (const float*)d_in[7];
    const float* gate_w1   = (const float*)d_in[8];
    const float* gate_b1   = (const float*)d_in[9];
    const float* gate_w2   = (const float*)d_in[10];
    const float* gate_b2   = (const float*)d_in[11];
    const float* ln_gamma  = (const float*)d_in[12];
    const float* ln_beta   = (const float*)d_in[13];
    float* out = (float*)d_out;

    cudaFuncSetAttribute(transform_kernel,
                         cudaFuncAttributeMaxDynamicSharedMemorySize,
                         TRANSFORM_SMEM);

    zero_kernel<<<1184, 256>>>(out);

    dim3 tgrid((N_NODES + 63) / 64, 2);
    transform_kernel<<<tgrid, 256, TRANSFORM_SMEM>>>(x_src, x_dst, W_src, W_dst, b_dst);

    gate_kernel<<<1184, 256>>>(edge_attr, gate_w1, gate_b1, gate_w2, gate_b2);

    scatter_kernel<<<1184, 256>>>(edge_src, edge_dst, out);

    finalize_kernel<<<(N_NODES * 32 + 255) / 256, 256>>>(out, ln_gamma, ln_beta);
}